// round 17
// baseline (speedup 1.0000x reference)
#include <cuda_runtime.h>
#include <cstdint>

// Problem constants
#define PB   64
#define PS   1024
#define PF   768
#define PH   12
#define PP2  64
#define HEADSZ 4096
#define QKVSTRIDE (PB * PH * HEADSZ)   // 3,145,728

__device__ float g_qkv[3LL * QKVSTRIDE];
__device__ float g_o[4096LL * PF];
__device__ int   g_sync[224];          // [0,192): qkv tile-group counters; [192,224): attn counters per bx

// ---------------------------------------------------------------------------
// PTX helpers
// ---------------------------------------------------------------------------
__device__ __forceinline__ void cp16(void* s, const void* g) {
    unsigned sa = (unsigned)__cvta_generic_to_shared(s);
    asm volatile("cp.async.cg.shared.global [%0], [%1], 16;\n" :: "r"(sa), "l"(g));
}
__device__ __forceinline__ void cp_commit() { asm volatile("cp.async.commit_group;\n"); }
template <int N>
__device__ __forceinline__ void cp_wait() { asm volatile("cp.async.wait_group %0;\n" :: "n"(N)); }

__device__ __forceinline__ void mma_tf32(float* c, const unsigned* a, const unsigned* b) {
    asm volatile(
        "mma.sync.aligned.m16n8k8.row.col.f32.tf32.tf32.f32 "
        "{%0,%1,%2,%3}, {%4,%5,%6,%7}, {%8,%9}, {%0,%1,%2,%3};"
        : "+f"(c[0]), "+f"(c[1]), "+f"(c[2]), "+f"(c[3])
        : "r"(a[0]), "r"(a[1]), "r"(a[2]), "r"(a[3]), "r"(b[0]), "r"(b[1]));
}

__device__ __forceinline__ void wait_flag(const int* p, int target) {
    while (*(volatile const int*)p < target) __nanosleep(200);
}

// Tail geometry (float4 units)
#define TPERB 184320                    // (PS-PP2)*(PF/4)
#define TROW  196608                    // PS*(PF/4)
#define TSKIP 12288                     // PP2*(PF/4)

// GEMM config (proven core)
#define BK   32
#define LDK  36
#define STAGEF ((128 + 128) * LDK)      // 9216 floats / stage
#define CPSTAGE 4096                    // 1024 float4 per copy stage
#define DSMEM  ((2 * STAGEF + 2 * CPSTAGE) * 4)   // 106496 B -> 2 CTAs/SM
#define NKI  (PF / BK)                  // 24
#define NCPCHUNK 20                     // 20 x 1024 float4 x 576 blocks = full tail

// ---------------------------------------------------------------------------
// GEMM body. MODE 0: QKV projection (+full tail copy). MODE 1: out projection.
// cpb: linear copy-share index (MODE 0).
// ---------------------------------------------------------------------------
template <int MODE>
__device__ __forceinline__ void gemm_body(
    int bx, int ny, int cpb, float* sm,
    const float* __restrict__ A,
    const float* __restrict__ W0, const float* __restrict__ W1, const float* __restrict__ W2,
    const float* __restrict__ b0, const float* __restrict__ b1, const float* __restrict__ b2,
    float* __restrict__ Cout)
{
    const int tid  = threadIdx.x;
    const int wid  = tid >> 5;
    const int lane = tid & 31;
    const int wm   = wid >> 2;
    const int wn   = wid & 3;
    const int g    = lane >> 2;
    const int t4   = lane & 3;

    const int m0 = bx * 128;
    const float* W; const float* bias; int nbw; int wsel = 0;
    if (MODE == 0) {
        wsel = ny / 6;
        nbw  = (ny % 6) * 128;
        W    = (wsel == 0) ? W0 : (wsel == 1 ? W1 : W2);
        bias = (wsel == 0) ? b0 : (wsel == 1 ? b1 : b2);
    } else {
        W = W0; bias = b0; nbw = ny * 128;
    }
    const float* Ap = (MODE == 0) ? A : g_o;

    const int cpbase = (MODE == 0) ? cpb * (NCPCHUNK * 1024) : 0;

    auto load_stage = [&](int buf, int k0, int ci) {
        float* As = sm + buf * STAGEF;
        float* Bs = As + 128 * LDK;
        #pragma unroll
        for (int p = 0; p < 4; p++) {
            int idx = tid + p * 256;
            int r = idx >> 3, c4 = (idx & 7) * 4;
            int gm = m0 + r;
            const float* ga = (MODE == 0)
                ? Ap + ((long long)(gm >> 6) * PS + (gm & 63)) * PF + k0 + c4
                : Ap + (long long)gm * PF + k0 + c4;
            cp16(&As[r * LDK + c4], ga);
        }
        #pragma unroll
        for (int p = 0; p < 4; p++) {
            int idx = tid + p * 256;
            int r = idx >> 3, c4 = (idx & 7) * 4;
            const float* gb = W + (long long)(nbw + r) * PF + k0 + c4;
            cp16(&Bs[r * LDK + c4], gb);
        }
        if (MODE == 0 && ci < NCPCHUNK) {
            float* cbuf = sm + 2 * STAGEF + (ci & 1) * CPSTAGE;
            #pragma unroll
            for (int q = 0; q < 4; q++) {
                int idx = cpbase + ci * 1024 + q * 256 + tid;
                int b = idx / TPERB;
                int rem = idx - b * TPERB;
                const float4* gsrc = (const float4*)A + ((long long)b * TROW + TSKIP + rem);
                cp16(&cbuf[(q * 256 + tid) * 4], gsrc);
            }
        }
    };

    float acc[4][4][4];
    #pragma unroll
    for (int mi = 0; mi < 4; mi++)
        #pragma unroll
        for (int ni = 0; ni < 4; ni++)
            #pragma unroll
            for (int q = 0; q < 4; q++) acc[mi][ni][q] = 0.0f;

    load_stage(0, 0, 0);
    cp_commit();

    for (int i = 0; i < NKI; i++) {
        if (i + 1 < NKI) {
            load_stage((i + 1) & 1, (i + 1) * BK, i + 1);
            cp_commit();
            cp_wait<1>();
        } else {
            cp_wait<0>();
        }
        __syncthreads();

        const float* As = sm + (i & 1) * STAGEF;
        const float* Bs = As + 128 * LDK;
        const float* ab = As + (wm * 64 + g) * LDK + t4;
        const float* bb = Bs + (wn * 32 + g) * LDK + t4;

        #pragma unroll
        for (int kk = 0; kk < BK; kk += 8) {
            unsigned af[4][4];
            #pragma unroll
            for (int mi = 0; mi < 4; mi++) {
                const float* p = ab + mi * 16 * LDK + kk;
                af[mi][0] = __float_as_uint(p[0]);
                af[mi][1] = __float_as_uint(p[8 * LDK]);
                af[mi][2] = __float_as_uint(p[4]);
                af[mi][3] = __float_as_uint(p[8 * LDK + 4]);
            }
            unsigned bf[4][2];
            #pragma unroll
            for (int ni = 0; ni < 4; ni++) {
                const float* p = bb + ni * 8 * LDK + kk;
                bf[ni][0] = __float_as_uint(p[0]);
                bf[ni][1] = __float_as_uint(p[4]);
            }
            #pragma unroll
            for (int mi = 0; mi < 4; mi++)
                #pragma unroll
                for (int ni = 0; ni < 4; ni++)
                    mma_tf32(acc[mi][ni], af[mi], bf[ni]);
        }

        if (MODE == 0 && i < NCPCHUNK) {
            const float* cbuf = sm + 2 * STAGEF + (i & 1) * CPSTAGE;
            #pragma unroll
            for (int q = 0; q < 4; q++) {
                int idx = cpbase + i * 1024 + q * 256 + tid;
                int b = idx / TPERB;
                int rem = idx - b * TPERB;
                float4 v = *reinterpret_cast<const float4*>(&cbuf[(q * 256 + tid) * 4]);
                __stcs((float4*)Cout + ((long long)b * TROW + TSKIP + rem), v);
            }
        }
        __syncthreads();
    }

    float2 bfrag[4];
    #pragma unroll
    for (int ni = 0; ni < 4; ni++)
        bfrag[ni] = *reinterpret_cast<const float2*>(bias + nbw + wn * 32 + ni * 8 + t4 * 2);

    #pragma unroll
    for (int mi = 0; mi < 4; mi++) {
        #pragma unroll
        for (int half = 0; half < 2; half++) {
            int gm = m0 + wm * 64 + mi * 16 + g + half * 8;
            int bb_ = gm >> 6, ss_ = gm & 63;
            #pragma unroll
            for (int ni = 0; ni < 4; ni++) {
                int n = nbw + wn * 32 + ni * 8 + t4 * 2;
                float2 v;
                v.x = acc[mi][ni][half * 2 + 0] + bfrag[ni].x;
                v.y = acc[mi][ni][half * 2 + 1] + bfrag[ni].y;
                if (MODE == 0) {
                    int h = n >> 6, d = n & 63;
                    float* dst = g_qkv + (long long)wsel * QKVSTRIDE
                               + (long long)(bb_ * PH + h) * HEADSZ + ss_ * 64 + d;
                    *reinterpret_cast<float2*>(dst) = v;
                } else {
                    float* dst = Cout + ((long long)bb_ * PS + ss_) * PF + n;
                    *reinterpret_cast<float2*>(dst) = v;
                }
            }
        }
    }
}

// ---------------------------------------------------------------------------
// Attention body for one (b,h); smem carved from dynamic buffer.
// ---------------------------------------------------------------------------
__device__ __forceinline__ void attn_body(int b, int h, float* sm) {
    float* sq = sm;
    float* sk = sm + 4096;
    float* ss = sm + 8192;

    const int tid = threadIdx.x;
    const float* qg = g_qkv + (long long)(b * PH + h) * HEADSZ;
    const float* kg = qg + (long long)QKVSTRIDE;
    const float* vg = kg + (long long)QKVSTRIDE;
    const int lane = tid & 31;

    for (int t = tid; t < 1024; t += 256)
        reinterpret_cast<float4*>(sq)[t] = reinterpret_cast<const float4*>(qg)[t];
    for (int t = tid; t < 1024; t += 256) {
        int j = t >> 4, d4 = (t & 15) * 4;
        float4 v = reinterpret_cast<const float4*>(kg)[t];
        *reinterpret_cast<float4*>(&sk[j * 64 + (d4 ^ ((j & 7) << 3))]) = v;
    }
    __syncthreads();

    #pragma unroll
    for (int t = 0; t < 16; t++) {
        int idx = tid + (t << 8);
        int i = idx >> 6, j = idx & 63;
        int sw = (j & 7) << 3;
        float s = 0.f;
        #pragma unroll
        for (int dd = 0; dd < 64; dd += 4) {
            float4 q4 = *reinterpret_cast<const float4*>(&sq[i * 64 + dd]);
            float4 k4 = *reinterpret_cast<const float4*>(&sk[j * 64 + (dd ^ sw)]);
            s += q4.x * k4.x + q4.y * k4.y + q4.z * k4.z + q4.w * k4.w;
        }
        ss[idx] = s * 0.125f;
    }
    __syncthreads();

    {
        int w = tid >> 5;
        #pragma unroll
        for (int rr = 0; rr < 8; rr++) {
            int i = w * 8 + rr;
            float x0 = ss[i * 64 + lane];
            float x1 = ss[i * 64 + 32 + lane];
            float m = fmaxf(x0, x1);
            #pragma unroll
            for (int o = 16; o; o >>= 1) m = fmaxf(m, __shfl_xor_sync(0xffffffffu, m, o));
            float e0 = __expf(x0 - m), e1 = __expf(x1 - m);
            float sum = e0 + e1;
            #pragma unroll
            for (int o = 16; o; o >>= 1) sum += __shfl_xor_sync(0xffffffffu, sum, o);
            float inv = 1.0f / sum;
            ss[i * 64 + lane]      = e0 * inv;
            ss[i * 64 + 32 + lane] = e1 * inv;
        }
    }
    __syncthreads();

    for (int t = tid; t < 1024; t += 256)
        reinterpret_cast<float4*>(sq)[t] = reinterpret_cast<const float4*>(vg)[t];
    __syncthreads();

    #pragma unroll
    for (int t = 0; t < 4; t++) {
        int gidx = tid + (t << 8);
        int i  = gidx >> 4;
        int d4 = (gidx & 15) * 4;
        float ox = 0.f, oy = 0.f, oz = 0.f, ow = 0.f;
        #pragma unroll 16
        for (int j = 0; j < 64; j++) {
            float a = ss[i * 64 + j];
            float4 v4 = *reinterpret_cast<const float4*>(&sq[j * 64 + d4]);
            ox += a * v4.x; oy += a * v4.y; oz += a * v4.z; ow += a * v4.w;
        }
        float4 o4; o4.x = ox; o4.y = oy; o4.z = oz; o4.w = ow;
        *reinterpret_cast<float4*>(&g_o[(long long)(b * 64 + i) * PF + h * 64 + d4]) = o4;
    }
}

// ---------------------------------------------------------------------------
// Mega kernel with bx-major dependency ordering:
//   [0,576)    gemm0 tiles, group k = bid/3 (k = bx*6+hp), wsel = bid%3.
//              Tiles for batch-pair bx are blocks [18*bx, 18*bx+18).
//   [576,1344) attention (b,h): waits g_sync[(b>>1)*6+(h>>1)] == 3.
//   [1344,1536) gemm1: tile bx waits attn counter g_sync[192+bx] == 24.
// All waits target lower-indexed blocks -> deadlock-free under in-order dispatch.
// ---------------------------------------------------------------------------
__global__ void __launch_bounds__(256, 2) mega_kernel(
    const float* __restrict__ x,
    const float* __restrict__ Wq, const float* __restrict__ bq,
    const float* __restrict__ Wk, const float* __restrict__ bk,
    const float* __restrict__ Wv, const float* __restrict__ bv,
    const float* __restrict__ Wo, const float* __restrict__ bo,
    float* __restrict__ out)
{
    extern __shared__ float sm[];
    const int bid = blockIdx.x;
    const int tid = threadIdx.x;

    if (bid < 576) {
        const int k    = bid / 3;         // tile group: bx*6 + hp
        const int wsel = bid - k * 3;
        const int bx   = k / 6;
        const int hp   = k - bx * 6;
        gemm_body<0>(bx, wsel * 6 + hp, bid, sm, x, Wq, Wk, Wv, bq, bk, bv, out);
        __threadfence();
        __syncthreads();
        if (tid == 0) atomicAdd(&g_sync[k], 1);
        return;
    }

    if (bid < 1344) {
        int idx = bid - 576;
        int b = idx / 12, h = idx - (idx / 12) * 12;
        int k = (b >> 1) * 6 + (h >> 1);
        if (tid == 0) {
            wait_flag(&g_sync[k], 3);                 // Q,K,V tile group done
            __threadfence();
        }
        __syncthreads();
        attn_body(b, h, sm);
        __threadfence();
        __syncthreads();
        if (tid == 0) atomicAdd(&g_sync[192 + (b >> 1)], 1);
        return;
    }

    {
        int t = bid - 1344;
        int bx = t & 31, ny = t >> 5;
        if (tid == 0) {
            wait_flag(&g_sync[192 + bx], 24);         // both batches, all heads
            __threadfence();
        }
        __syncthreads();
        gemm_body<1>(bx, ny, 0, sm, nullptr, Wo, nullptr, nullptr,
                     bo, nullptr, nullptr, out);
    }
}

// ---------------------------------------------------------------------------
extern "C" void kernel_launch(void* const* d_in, const int* in_sizes, int n_in,
                              void* d_out, int out_size) {
    const float* x  = (const float*)d_in[0];
    const float* Wq = (const float*)d_in[1];
    const float* bq = (const float*)d_in[2];
    const float* Wk = (const float*)d_in[3];
    const float* bk = (const float*)d_in[4];
    const float* Wv = (const float*)d_in[5];
    const float* bv = (const float*)d_in[6];
    const float* Wo = (const float*)d_in[7];
    const float* bo = (const float*)d_in[8];
    float* out = (float*)d_out;

    cudaFuncSetAttribute(mega_kernel, cudaFuncAttributeMaxDynamicSharedMemorySize, DSMEM);

    // Reset cross-phase flags (graph-capturable memset node, replay-safe)
    void* sync_ptr = nullptr;
    cudaGetSymbolAddress(&sync_ptr, g_sync);
    cudaMemsetAsync(sync_ptr, 0, 224 * sizeof(int));

    mega_kernel<<<1536, 256, DSMEM>>>(x, Wq, bq, Wk, bk, Wv, bv, Wo, bo, out);
}